// round 2
// baseline (speedup 1.0000x reference)
#include <cuda_runtime.h>
#include <cstdint>

// ---------------------------------------------------------------------------
// Problem constants
// ---------------------------------------------------------------------------
#define B_      4
#define S_      4096
#define D_      1024
#define H_      16
#define M_TOTAL (B_ * S_)     // 16384 tokens
#define N_W     1024
#define K_TOTAL 1024

// GEMM tiling
#define BM 128
#define BN 128
#define BK 32
#define NITER (K_TOTAL / BK)   // 32

// SMEM padding (floats): A rows BK+4 -> conflict-free A frags;
// B rows BN+8 -> conflict-free B frags.
#define APAD 4
#define BPAD 8
#define AROW (BK + APAD)        // 36
#define BROW (BN + BPAD)        // 136
#define A_TILE_F (BM * AROW)    // 4608 floats
#define B_TILE_F (BK * BROW)    // 4352 floats
#define SMEM_FLOATS (2 * (A_TILE_F + B_TILE_F))
#define SMEM_BYTES  (SMEM_FLOATS * 4)   // 71680

// QKV scratch: [3][M_TOTAL][N_W] fp32 = 201 MB
__device__ float g_qkv[3ull * M_TOTAL * N_W];

// ---------------------------------------------------------------------------
// Helpers
// ---------------------------------------------------------------------------
__device__ __forceinline__ uint32_t smem_u32(const void* p) {
    uint32_t a;
    asm("{ .reg .u64 t; cvta.to.shared.u64 t, %1; cvt.u32.u64 %0, t; }" : "=r"(a) : "l"(p));
    return a;
}

#define CP_ASYNC_16(dst_u32, src_ptr) \
    asm volatile("cp.async.cg.shared.global [%0], [%1], 16;" \
                 :: "r"(dst_u32), "l"(src_ptr) : "memory")
#define CP_COMMIT() asm volatile("cp.async.commit_group;" ::: "memory")
#define CP_WAIT(n)  asm volatile("cp.async.wait_group %0;" :: "n"(n) : "memory")

// fp32 -> tf32 with round-to-nearest (zero-mean error; raw truncation would
// bias magnitudes low by ~1e-3 and eat the whole error budget).
__device__ __forceinline__ uint32_t f2tf32(float f) {
    uint32_t u;
    asm("cvt.rna.tf32.f32 %0, %1;" : "=r"(u) : "f"(f));
    return u;
}

// m16n8k8 tf32 MMA (legacy tensor-core path; legal on target sm_100)
__device__ __forceinline__ void mma_tf32(float* d, const uint32_t* a, const uint32_t* b) {
    asm volatile(
        "mma.sync.aligned.m16n8k8.row.col.f32.tf32.tf32.f32 "
        "{%0,%1,%2,%3}, {%4,%5,%6,%7}, {%8,%9}, {%0,%1,%2,%3};"
        : "+f"(d[0]), "+f"(d[1]), "+f"(d[2]), "+f"(d[3])
        : "r"(a[0]), "r"(a[1]), "r"(a[2]), "r"(a[3]),
          "r"(b[0]), "r"(b[1]));
}

// ---------------------------------------------------------------------------
// Fused QKV GEMM:  g_qkv[w] = x @ W[w] + b[w]
// Grid: (24 n-tiles [8 per weight], 128 m-tiles), 256 threads.
// Double-buffered cp.async pipeline; warp tile 64x32 (2x4 warp grid).
// ---------------------------------------------------------------------------
__global__ void __launch_bounds__(256, 2)
qkv_gemm_kernel(const float* __restrict__ x,
                const float* __restrict__ Wq, const float* __restrict__ Wk,
                const float* __restrict__ Wv,
                const float* __restrict__ bq, const float* __restrict__ bk,
                const float* __restrict__ bv)
{
    extern __shared__ float smem[];
    float* As = smem;                       // [2][BM][AROW]
    float* Bs = smem + 2 * A_TILE_F;        // [2][BK][BROW]
    const uint32_t sA = smem_u32(As);
    const uint32_t sB = smem_u32(Bs);

    const int tid = threadIdx.x;
    const int wid = tid >> 5;
    const int lane = tid & 31;
    const int r = lane >> 2;                // 0..7
    const int c = lane & 3;                 // 0..3

    const int ntile = blockIdx.x;           // 0..23
    const int mtile = blockIdx.y;           // 0..127
    const int wsel  = ntile >> 3;           // 0=Q,1=K,2=V
    const int n0    = (ntile & 7) * BN;
    const int m0    = mtile * BM;
    const float* W    = (wsel == 0) ? Wq : (wsel == 1 ? Wk : Wv);
    const float* bias = (wsel == 0) ? bq : (wsel == 1 ? bk : bv);

    const int wm = wid & 1;                 // 0..1 -> 64-row group
    const int wn = wid >> 1;                // 0..3 -> 32-col group

    // --- cp.async tile loaders: 1024 16B chunks each, 4 per thread ---
    // A chunk idx -> row = idx>>3 (0..127), q = idx&7 (16B within 128B row)
    // B chunk idx -> k   = idx>>5 (0..31),  q = idx&31 (16B within 512B row)
    auto load_tiles = [&](int kc, int buf) {
        const float* Ag = x + (size_t)m0 * K_TOTAL + (size_t)kc * BK;
        const float* Bg = W + (size_t)kc * BK * N_W + n0;
        #pragma unroll
        for (int i = 0; i < 4; i++) {
            int idx = tid + i * 256;
            int arow = idx >> 3, aq = idx & 7;
            uint32_t adst = sA + (uint32_t)(((buf * BM + arow) * AROW + aq * 4) * 4);
            CP_ASYNC_16(adst, Ag + (size_t)arow * K_TOTAL + aq * 4);
        }
        #pragma unroll
        for (int i = 0; i < 4; i++) {
            int idx = tid + i * 256;
            int bk = idx >> 5, bq_ = idx & 31;
            uint32_t bdst = sB + (uint32_t)(((buf * BK + bk) * BROW + bq_ * 4) * 4);
            CP_ASYNC_16(bdst, Bg + (size_t)bk * N_W + bq_ * 4);
        }
        CP_COMMIT();
    };

    float acc[4][4][4];
    #pragma unroll
    for (int mt = 0; mt < 4; mt++)
        #pragma unroll
        for (int nt = 0; nt < 4; nt++)
            #pragma unroll
            for (int i = 0; i < 4; i++) acc[mt][nt][i] = 0.f;

    load_tiles(0, 0);

    for (int kc = 0; kc < NITER; kc++) {
        const int buf = kc & 1;
        if (kc + 1 < NITER) {
            load_tiles(kc + 1, buf ^ 1);
            CP_WAIT(1);
        } else {
            CP_WAIT(0);
        }
        __syncthreads();

        const float* A_s = As + buf * A_TILE_F + (wm * 64) * AROW;
        const float* B_s = Bs + buf * B_TILE_F;

        #pragma unroll
        for (int ks = 0; ks < 4; ks++) {
            const int k0 = ks * 8;
            uint32_t af[4][4];
            #pragma unroll
            for (int mt = 0; mt < 4; mt++) {
                const float* ap = A_s + (mt * 16 + r) * AROW + k0 + c;
                af[mt][0] = f2tf32(ap[0]);
                af[mt][1] = f2tf32(ap[8 * AROW]);
                af[mt][2] = f2tf32(ap[4]);
                af[mt][3] = f2tf32(ap[8 * AROW + 4]);
            }
            uint32_t bf[4][2];
            #pragma unroll
            for (int nt = 0; nt < 4; nt++) {
                const float* bp = B_s + (k0 + c) * BROW + wn * 32 + nt * 8 + r;
                bf[nt][0] = f2tf32(bp[0]);
                bf[nt][1] = f2tf32(bp[4 * BROW]);
            }
            #pragma unroll
            for (int mt = 0; mt < 4; mt++)
                #pragma unroll
                for (int nt = 0; nt < 4; nt++)
                    mma_tf32(acc[mt][nt], af[mt], bf[nt]);
        }
        __syncthreads();
    }

    // --- Epilogue: acc -> g_qkv (+bias) ---
    float* dst_w = g_qkv + (size_t)wsel * M_TOTAL * N_W;
    #pragma unroll
    for (int mt = 0; mt < 4; mt++) {
        const int row0 = m0 + wm * 64 + mt * 16 + r;
        #pragma unroll
        for (int nt = 0; nt < 4; nt++) {
            const int col = n0 + wn * 32 + nt * 8 + c * 2;
            const float b0 = __ldg(bias + col);
            const float b1 = __ldg(bias + col + 1);
            float2 v0 = make_float2(acc[mt][nt][0] + b0, acc[mt][nt][1] + b1);
            float2 v1 = make_float2(acc[mt][nt][2] + b0, acc[mt][nt][3] + b1);
            *(float2*)(dst_w + (size_t)row0 * N_W + col)       = v0;
            *(float2*)(dst_w + (size_t)(row0 + 8) * N_W + col) = v1;
        }
    }
}

// ---------------------------------------------------------------------------
// Head-attention: per token t, q/k/v are [16 heads][64]; scores [16,16],
// softmax over j, ctx [16,64]. One block (512 thr) per token, warp per head.
// ---------------------------------------------------------------------------
__global__ void __launch_bounds__(512, 2)
attn_kernel(float* __restrict__ out)
{
    const int t   = blockIdx.x;
    const int tid = threadIdx.x;
    const int wid = tid >> 5;
    const int lid = tid & 31;

    __shared__ float sk[16 * 65];   // padded rows -> conflict-free dot loads
    __shared__ float sv[16 * 64];
    __shared__ float sp[16][16];

    const float* qg = g_qkv + (size_t)t * N_W;
    const float* kg = g_qkv + (size_t)M_TOTAL * N_W + (size_t)t * N_W;
    const float* vg = g_qkv + 2ull * M_TOTAL * N_W + (size_t)t * N_W;

    for (int i = tid; i < 1024; i += 512) {
        sk[(i >> 6) * 65 + (i & 63)] = kg[i];
        sv[i] = vg[i];
    }
    __syncthreads();

    const int h = wid;   // head = query index i
    if (lid < 16) {
        const float* qh = qg + h * 64;
        const float* kj = sk + lid * 65;
        float s = 0.f;
        #pragma unroll
        for (int d = 0; d < 64; d++) s = fmaf(__ldg(qh + d), kj[d], s);
        s *= 0.125f;   // 1/sqrt(64)
        float m = s;
        #pragma unroll
        for (int o = 8; o > 0; o >>= 1) m = fmaxf(m, __shfl_xor_sync(0xffffu, m, o, 16));
        float e = __expf(s - m);
        float sum = e;
        #pragma unroll
        for (int o = 8; o > 0; o >>= 1) sum += __shfl_xor_sync(0xffffu, sum, o, 16);
        sp[h][lid] = e / sum;
    }
    __syncwarp();

    float a0 = 0.f, a1 = 0.f;
    #pragma unroll
    for (int j = 0; j < 16; j++) {
        float pj = sp[h][j];
        a0 = fmaf(pj, sv[j * 64 + lid], a0);
        a1 = fmaf(pj, sv[j * 64 + lid + 32], a1);
    }
    float* ot = out + (size_t)t * N_W + h * 64;
    ot[lid]      = a0;
    ot[lid + 32] = a1;
}

// ---------------------------------------------------------------------------
// Launch
// ---------------------------------------------------------------------------
extern "C" void kernel_launch(void* const* d_in, const int* in_sizes, int n_in,
                              void* d_out, int out_size)
{
    const float* x  = (const float*)d_in[0];
    const float* Wq = (const float*)d_in[1];
    const float* bq = (const float*)d_in[2];
    const float* Wk = (const float*)d_in[3];
    const float* bk = (const float*)d_in[4];
    const float* Wv = (const float*)d_in[5];
    const float* bv = (const float*)d_in[6];
    float* out = (float*)d_out;

    cudaFuncSetAttribute(qkv_gemm_kernel,
                         cudaFuncAttributeMaxDynamicSharedMemorySize, SMEM_BYTES);

    dim3 grid(24, 128);
    qkv_gemm_kernel<<<grid, 256, SMEM_BYTES>>>(x, Wq, Wk, Wv, bq, bk, bv);
    attn_kernel<<<M_TOTAL, 512>>>(out);
}

// round 3
// speedup vs baseline: 1.2910x; 1.2910x over previous
#include <cuda_runtime.h>
#include <cstdint>

// ---------------------------------------------------------------------------
// Problem constants
// ---------------------------------------------------------------------------
#define M_TOTAL 16384
#define N_W     1024
#define K_TOTAL 1024

// GEMM tiling
#define BM 128
#define BN 128
#define BK 32
#define NITER (K_TOTAL / BK)   // 32

#define AROW 40                 // BK + 8 pad -> conflict-free v2 A-frag loads
#define BROW 136                // BN + 8 pad -> conflict-free B-frag loads
#define A_TILE_F (BM * AROW)    // 5120 floats
#define B_TILE_F (BK * BROW)    // 4352 floats
#define SMEM_BYTES (2 * (A_TILE_F + B_TILE_F) * 4)   // 75776

// Scratch
__device__ float g_qkv[3ull * M_TOTAL * N_W];   // QKV projections
__device__ float g_xr[(size_t)M_TOTAL * K_TOTAL]; // x: tf32-rounded, k-interleaved
__device__ float g_wr[3ull * K_TOTAL * N_W];      // W: tf32-rounded

// ---------------------------------------------------------------------------
// Helpers
// ---------------------------------------------------------------------------
__device__ __forceinline__ uint32_t smem_u32(const void* p) {
    uint32_t a;
    asm("{ .reg .u64 t; cvta.to.shared.u64 t, %1; cvt.u32.u64 %0, t; }" : "=r"(a) : "l"(p));
    return a;
}

#define CP_ASYNC_16(dst_u32, src_ptr) \
    asm volatile("cp.async.cg.shared.global [%0], [%1], 16;" \
                 :: "r"(dst_u32), "l"(src_ptr) : "memory")
#define CP_COMMIT() asm volatile("cp.async.commit_group;" ::: "memory")
#define CP_WAIT(n)  asm volatile("cp.async.wait_group %0;" :: "n"(n) : "memory")

__device__ __forceinline__ float tf32r(float f) {
    uint32_t u;
    asm("cvt.rna.tf32.f32 %0, %1;" : "=r"(u) : "f"(f));
    return __uint_as_float(u);
}

__device__ __forceinline__ void mma_tf32(float* d, const uint32_t* a, const uint32_t* b) {
    asm volatile(
        "mma.sync.aligned.m16n8k8.row.col.f32.tf32.tf32.f32 "
        "{%0,%1,%2,%3}, {%4,%5,%6,%7}, {%8,%9}, {%0,%1,%2,%3};"
        : "+f"(d[0]), "+f"(d[1]), "+f"(d[2]), "+f"(d[3])
        : "r"(a[0]), "r"(a[1]), "r"(a[2]), "r"(a[3]),
          "r"(b[0]), "r"(b[1]));
}

// ---------------------------------------------------------------------------
// Pre-round kernels: tf32-round once, outside the GEMM hot loop.
// x additionally gets per-8-group k-interleave: pos(k) = 2*(k&3) + (k>>2),
// so an MMA thread's (a0,a2)/(a1,a3) fragment pairs are SMEM-adjacent.
// ---------------------------------------------------------------------------
__global__ void __launch_bounds__(256)
round_x_kernel(const float* __restrict__ x)
{
    size_t g = (size_t)blockIdx.x * 256 + threadIdx.x;   // 8-float group id
    const float4 a = *(const float4*)(x + g * 8);
    const float4 b = *(const float4*)(x + g * 8 + 4);
    float4 o0, o1;
    o0.x = tf32r(a.x); o0.y = tf32r(b.x); o0.z = tf32r(a.y); o0.w = tf32r(b.y);
    o1.x = tf32r(a.z); o1.y = tf32r(b.z); o1.z = tf32r(a.w); o1.w = tf32r(b.w);
    *(float4*)(g_xr + g * 8)     = o0;
    *(float4*)(g_xr + g * 8 + 4) = o1;
}

__global__ void __launch_bounds__(256)
round_w_kernel(const float* __restrict__ Wq, const float* __restrict__ Wk,
               const float* __restrict__ Wv)
{
    size_t i = (size_t)blockIdx.x * 256 + threadIdx.x;   // float4 id, 0..786431
    const size_t per = (size_t)K_TOTAL * N_W / 4;        // 262144
    const float* src = (i < per) ? Wq : (i < 2 * per ? Wk : Wv);
    size_t r = (i < per) ? i : (i < 2 * per ? i - per : i - 2 * per);
    float4 v = *(const float4*)(src + r * 4);
    v.x = tf32r(v.x); v.y = tf32r(v.y); v.z = tf32r(v.z); v.w = tf32r(v.w);
    *(float4*)(g_wr + i * 4) = v;
}

// ---------------------------------------------------------------------------
// Fused QKV GEMM: g_qkv[w] = x @ W[w] + b[w]. Inputs pre-rounded: hot loop
// is pure LDS + MMA. Grid (24, 128), 256 threads, warp tile 64x32.
// ---------------------------------------------------------------------------
__global__ void __launch_bounds__(256, 2)
qkv_gemm_kernel(const float* __restrict__ bq, const float* __restrict__ bk,
                const float* __restrict__ bv)
{
    extern __shared__ float smem[];
    float* As = smem;                       // [2][BM][AROW], k-interleaved rows
    float* Bs = smem + 2 * A_TILE_F;        // [2][BK][BROW]
    const uint32_t sA = smem_u32(As);
    const uint32_t sB = smem_u32(Bs);

    const int tid = threadIdx.x;
    const int wid = tid >> 5;
    const int lane = tid & 31;
    const int r = lane >> 2;                // 0..7
    const int c = lane & 3;                 // 0..3

    const int ntile = blockIdx.x;           // 0..23
    const int mtile = blockIdx.y;           // 0..127
    const int wsel  = ntile >> 3;           // 0=Q,1=K,2=V
    const int n0    = (ntile & 7) * BN;
    const int m0    = mtile * BM;
    const float* W    = g_wr + (size_t)wsel * K_TOTAL * N_W;
    const float* bias = (wsel == 0) ? bq : (wsel == 1 ? bk : bv);

    const int wm = wid & 1;
    const int wn = wid >> 1;

    auto load_tiles = [&](int kc, int buf) {
        const float* Ag = g_xr + (size_t)m0 * K_TOTAL + (size_t)kc * BK;
        const float* Bg = W + (size_t)kc * BK * N_W + n0;
        #pragma unroll
        for (int i = 0; i < 4; i++) {
            int idx = tid + i * 256;
            int arow = idx >> 3, aq = idx & 7;
            uint32_t adst = sA + (uint32_t)(((buf * BM + arow) * AROW + aq * 4) * 4);
            CP_ASYNC_16(adst, Ag + (size_t)arow * K_TOTAL + aq * 4);
        }
        #pragma unroll
        for (int i = 0; i < 4; i++) {
            int idx = tid + i * 256;
            int bk = idx >> 5, bq_ = idx & 31;
            uint32_t bdst = sB + (uint32_t)(((buf * BK + bk) * BROW + bq_ * 4) * 4);
            CP_ASYNC_16(bdst, Bg + (size_t)bk * N_W + bq_ * 4);
        }
        CP_COMMIT();
    };

    float acc[4][4][4];
    #pragma unroll
    for (int mt = 0; mt < 4; mt++)
        #pragma unroll
        for (int nt = 0; nt < 4; nt++)
            #pragma unroll
            for (int i = 0; i < 4; i++) acc[mt][nt][i] = 0.f;

    load_tiles(0, 0);

    for (int kc = 0; kc < NITER; kc++) {
        const int buf = kc & 1;
        if (kc + 1 < NITER) {
            load_tiles(kc + 1, buf ^ 1);
            CP_WAIT(1);
        } else {
            CP_WAIT(0);
        }
        __syncthreads();

        const float* A_s = As + buf * A_TILE_F + (wm * 64 + r) * AROW;
        const float* B_s = Bs + buf * B_TILE_F;

        #pragma unroll
        for (int ks = 0; ks < 4; ks++) {
            const int k0 = ks * 8;
            uint32_t af[4][4];
            #pragma unroll
            for (int mt = 0; mt < 4; mt++) {
                // interleaved row: pos 2c -> k=c, pos 2c+1 -> k=c+4
                float2 p0 = *(const float2*)(A_s + (mt * 16) * AROW + k0 + 2 * c);
                float2 p1 = *(const float2*)(A_s + (mt * 16 + 8) * AROW + k0 + 2 * c);
                af[mt][0] = __float_as_uint(p0.x);  // (r,   c)
                af[mt][1] = __float_as_uint(p1.x);  // (r+8, c)
                af[mt][2] = __float_as_uint(p0.y);  // (r,   c+4)
                af[mt][3] = __float_as_uint(p1.y);  // (r+8, c+4)
            }
            uint32_t bf[4][2];
            #pragma unroll
            for (int nt = 0; nt < 4; nt++) {
                const float* bp = B_s + (k0 + c) * BROW + wn * 32 + nt * 8 + r;
                bf[nt][0] = __float_as_uint(bp[0]);
                bf[nt][1] = __float_as_uint(bp[4 * BROW]);
            }
            #pragma unroll
            for (int mt = 0; mt < 4; mt++)
                #pragma unroll
                for (int nt = 0; nt < 4; nt++)
                    mma_tf32(acc[mt][nt], af[mt], bf[nt]);
        }
        __syncthreads();
    }

    float* dst_w = g_qkv + (size_t)wsel * M_TOTAL * N_W;
    #pragma unroll
    for (int mt = 0; mt < 4; mt++) {
        const int row0 = m0 + wm * 64 + mt * 16 + r;
        #pragma unroll
        for (int nt = 0; nt < 4; nt++) {
            const int col = n0 + wn * 32 + nt * 8 + c * 2;
            const float b0 = __ldg(bias + col);
            const float b1 = __ldg(bias + col + 1);
            float2 v0 = make_float2(acc[mt][nt][0] + b0, acc[mt][nt][1] + b1);
            float2 v1 = make_float2(acc[mt][nt][2] + b0, acc[mt][nt][3] + b1);
            *(float2*)(dst_w + (size_t)row0 * N_W + col)       = v0;
            *(float2*)(dst_w + (size_t)(row0 + 8) * N_W + col) = v1;
        }
    }
}

// ---------------------------------------------------------------------------
// Head-attention, throughput version.
// Block = 128 threads = 8 tokens x 16 worker threads.
// Worker sub = (ib, jb): scores block [ib*4..+4][jb*4..+4] from SMEM float4s,
// quad-shuffle softmax, probs stored transposed, ctx cols sub*4..+4 over all
// 16 rows, fully coalesced output stores.
// ---------------------------------------------------------------------------
#define TPB_T 8
#define RS    68                    // q/k/v smem row stride (floats)
#define TSTR  (16 * RS + 4)         // token stride: 1092 floats
#define PSTR  16                    // probs row stride
#define PTOK  (16 * PSTR + 4)       // probs token stride: 260
#define ATTN_SMEM_F (3 * TPB_T * TSTR + TPB_T * PTOK)   // 28288 floats
#define ATTN_SMEM_B (ATTN_SMEM_F * 4)                   // 113152 bytes

__global__ void __launch_bounds__(128, 2)
attn_kernel(float* __restrict__ out)
{
    extern __shared__ float sm[];
    float* sq  = sm;
    float* sk  = sm + TPB_T * TSTR;
    float* sv  = sm + 2 * TPB_T * TSTR;
    float* spT = sm + 3 * TPB_T * TSTR;

    const int tid = threadIdx.x;
    const int t0 = blockIdx.x * TPB_T;

    // Stage q,k,v: 2048 float4 per tensor, coalesced.
    {
        const float* qg = g_qkv + (size_t)t0 * N_W;
        const float* kg = g_qkv + (size_t)M_TOTAL * N_W + (size_t)t0 * N_W;
        const float* vg = g_qkv + 2ull * M_TOTAL * N_W + (size_t)t0 * N_W;
        #pragma unroll
        for (int i = 0; i < 16; i++) {
            int idx = tid + i * 128;            // 0..2047
            int tok = idx >> 8, rem = idx & 255;
            int row = rem >> 4, dq = rem & 15;
            int sa = tok * TSTR + row * RS + dq * 4;
            size_t ga = (size_t)idx * 4;        // contiguous within the 8-token span
            *(float4*)(sq + sa) = *(const float4*)(qg + ga);
            *(float4*)(sk + sa) = *(const float4*)(kg + ga);
            *(float4*)(sv + sa) = *(const float4*)(vg + ga);
        }
    }
    __syncthreads();

    const int tt = tid >> 4;
    const int sub = tid & 15;
    const int ib = sub >> 2;
    const int jb = sub & 3;

    // ---- scores: 4x4 block ----
    float s[4][4];
    #pragma unroll
    for (int i = 0; i < 4; i++)
        #pragma unroll
        for (int j = 0; j < 4; j++) s[i][j] = 0.f;

    {
        const float* qp = sq + tt * TSTR + (ib * 4) * RS;
        const float* kp = sk + tt * TSTR + (jb * 4) * RS;
        #pragma unroll
        for (int dq = 0; dq < 16; dq++) {
            float4 qa[4], ka[4];
            #pragma unroll
            for (int i = 0; i < 4; i++) qa[i] = *(const float4*)(qp + i * RS + dq * 4);
            #pragma unroll
            for (int j = 0; j < 4; j++) ka[j] = *(const float4*)(kp + j * RS + dq * 4);
            #pragma unroll
            for (int i = 0; i < 4; i++)
                #pragma unroll
                for (int j = 0; j < 4; j++) {
                    s[i][j] = fmaf(qa[i].x, ka[j].x, s[i][j]);
                    s[i][j] = fmaf(qa[i].y, ka[j].y, s[i][j]);
                    s[i][j] = fmaf(qa[i].z, ka[j].z, s[i][j]);
                    s[i][j] = fmaf(qa[i].w, ka[j].w, s[i][j]);
                }
        }
    }

    // ---- softmax over j (row-wise, 4 jb-lanes per row are adjacent) ----
    float p[4][4];
    #pragma unroll
    for (int i = 0; i < 4; i++) {
        float sc[4];
        #pragma unroll
        for (int j = 0; j < 4; j++) sc[j] = s[i][j] * 0.125f;
        float m = fmaxf(fmaxf(sc[0], sc[1]), fmaxf(sc[2], sc[3]));
        m = fmaxf(m, __shfl_xor_sync(0xffffffffu, m, 1));
        m = fmaxf(m, __shfl_xor_sync(0xffffffffu, m, 2));
        float sum = 0.f;
        #pragma unroll
        for (int j = 0; j < 4; j++) { p[i][j] = __expf(sc[j] - m); sum += p[i][j]; }
        sum += __shfl_xor_sync(0xffffffffu, sum, 1);
        sum += __shfl_xor_sync(0xffffffffu, sum, 2);
        float inv = __frcp_rn(sum);
        #pragma unroll
        for (int j = 0; j < 4; j++) p[i][j] *= inv;
    }
    // store transposed: spT[tok][j][i]
    {
        float* pt = spT + tt * PTOK;
        #pragma unroll
        for (int j = 0; j < 4; j++) {
            float4 v = make_float4(p[0][j], p[1][j], p[2][j], p[3][j]);
            *(float4*)(pt + (jb * 4 + j) * PSTR + ib * 4) = v;
        }
    }
    __syncwarp();

    // ---- ctx: all 16 rows x 4 cols (c0 = sub*4) ----
    {
        const int c0 = sub * 4;
        const float* pt = spT + tt * PTOK;
        const float* vp = sv + tt * TSTR + c0;
        float4 acc[16];
        #pragma unroll
        for (int i = 0; i < 16; i++) acc[i] = make_float4(0.f, 0.f, 0.f, 0.f);
        #pragma unroll
        for (int j = 0; j < 16; j++) {
            float4 vj = *(const float4*)(vp + j * RS);
            const float* pr = pt + j * PSTR;
            float4 p0 = *(const float4*)(pr);
            float4 p1 = *(const float4*)(pr + 4);
            float4 p2 = *(const float4*)(pr + 8);
            float4 p3 = *(const float4*)(pr + 12);
            const float pj[16] = {p0.x,p0.y,p0.z,p0.w, p1.x,p1.y,p1.z,p1.w,
                                  p2.x,p2.y,p2.z,p2.w, p3.x,p3.y,p3.z,p3.w};
            #pragma unroll
            for (int i = 0; i < 16; i++) {
                acc[i].x = fmaf(pj[i], vj.x, acc[i].x);
                acc[i].y = fmaf(pj[i], vj.y, acc[i].y);
                acc[i].z = fmaf(pj[i], vj.z, acc[i].z);
                acc[i].w = fmaf(pj[i], vj.w, acc[i].w);
            }
        }
        float* ob = out + (size_t)(t0 + tt) * N_W + c0;
        #pragma unroll
        for (int i = 0; i < 16; i++)
            *(float4*)(ob + i * 64) = acc[i];   // 16 lanes/token -> 256B rows
    }
}

// ---------------------------------------------------------------------------
// Launch
// ---------------------------------------------------------------------------
extern "C" void kernel_launch(void* const* d_in, const int* in_sizes, int n_in,
                              void* d_out, int out_size)
{
    const float* x  = (const float*)d_in[0];
    const float* Wq = (const float*)d_in[1];
    const float* bq = (const float*)d_in[2];
    const float* Wk = (const float*)d_in[3];
    const float* bk = (const float*)d_in[4];
    const float* Wv = (const float*)d_in[5];
    const float* bv = (const float*)d_in[6];
    float* out = (float*)d_out;

    cudaFuncSetAttribute(qkv_gemm_kernel,
                         cudaFuncAttributeMaxDynamicSharedMemorySize, SMEM_BYTES);
    cudaFuncSetAttribute(attn_kernel,
                         cudaFuncAttributeMaxDynamicSharedMemorySize, ATTN_SMEM_B);

    round_x_kernel<<<(M_TOTAL * K_TOTAL / 8) / 256, 256>>>(x);
    round_w_kernel<<<(3 * K_TOTAL * N_W / 4) / 256, 256>>>(Wq, Wk, Wv);

    dim3 grid(24, 128);
    qkv_gemm_kernel<<<grid, 256, SMEM_BYTES>>>(bq, bk, bv);
    attn_kernel<<<M_TOTAL / TPB_T, 128, ATTN_SMEM_B>>>(out);
}

// round 4
// speedup vs baseline: 1.3531x; 1.0480x over previous
#include <cuda_runtime.h>
#include <cstdint>

// ---------------------------------------------------------------------------
// Problem constants
// ---------------------------------------------------------------------------
#define M_TOTAL 16384
#define N_W     1024
#define K_TOTAL 1024

// GEMM tiling: CTA 128x128, 4 warps of 64x64, BK=32
#define BM 128
#define BN 128
#define BK 32
#define NITER (K_TOTAL / BK)   // 32

#define TROW 40                 // 32 + 8 pad: conflict-free LDS.64 frag loads
#define TILE_F (128 * TROW)     // 5120 floats (A and B tiles identical shape)
#define SMEM_BYTES (4 * TILE_F * 4)   // 2 stages x (A+B) = 81920 B

// Scratch
__device__ float g_qkv[3ull * M_TOTAL * N_W];     // QKV projections
__device__ float g_xr[(size_t)M_TOTAL * K_TOTAL]; // x: tf32, k-interleaved
__device__ float g_wt[3ull * K_TOTAL * N_W];      // W: tf32, [w][nb][kc][n][32] tiles

// ---------------------------------------------------------------------------
// Helpers
// ---------------------------------------------------------------------------
__device__ __forceinline__ uint32_t smem_u32(const void* p) {
    uint32_t a;
    asm("{ .reg .u64 t; cvta.to.shared.u64 t, %1; cvt.u32.u64 %0, t; }" : "=r"(a) : "l"(p));
    return a;
}

#define CP_ASYNC_16(dst_u32, src_ptr) \
    asm volatile("cp.async.cg.shared.global [%0], [%1], 16;" \
                 :: "r"(dst_u32), "l"(src_ptr) : "memory")
#define CP_COMMIT() asm volatile("cp.async.commit_group;" ::: "memory")
#define CP_WAIT(n)  asm volatile("cp.async.wait_group %0;" :: "n"(n) : "memory")

__device__ __forceinline__ float tf32r(float f) {
    uint32_t u;
    asm("cvt.rna.tf32.f32 %0, %1;" : "=r"(u) : "f"(f));
    return __uint_as_float(u);
}

__device__ __forceinline__ void mma_tf32(float* d, const uint32_t* a, const uint32_t* b) {
    asm volatile(
        "mma.sync.aligned.m16n8k8.row.col.f32.tf32.tf32.f32 "
        "{%0,%1,%2,%3}, {%4,%5,%6,%7}, {%8,%9}, {%0,%1,%2,%3};"
        : "+f"(d[0]), "+f"(d[1]), "+f"(d[2]), "+f"(d[3])
        : "r"(a[0]), "r"(a[1]), "r"(a[2]), "r"(a[3]),
          "r"(b[0]), "r"(b[1]));
}

// ---------------------------------------------------------------------------
// round_x: tf32-round + per-8-group k-interleave pos(k)=2*(k&3)+(k>>2),
// so a fragment pair (k, k+4) is SMEM-adjacent -> LDS.64.
// ---------------------------------------------------------------------------
__global__ void __launch_bounds__(256)
round_x_kernel(const float* __restrict__ x)
{
    size_t g = (size_t)blockIdx.x * 256 + threadIdx.x;   // 8-float group id
    const float4 a = *(const float4*)(x + g * 8);
    const float4 b = *(const float4*)(x + g * 8 + 4);
    float4 o0, o1;
    o0.x = tf32r(a.x); o0.y = tf32r(b.x); o0.z = tf32r(a.y); o0.w = tf32r(b.y);
    o1.x = tf32r(a.z); o1.y = tf32r(b.z); o1.z = tf32r(a.w); o1.w = tf32r(b.w);
    *(float4*)(g_xr + g * 8)     = o0;
    *(float4*)(g_xr + g * 8 + 4) = o1;
}

// ---------------------------------------------------------------------------
// round_w: tf32-round + transpose W[k][n] into n-major, k-interleaved tiles:
// g_wt tile (w, nb, kc) = [n in 0..127][32 k-interleaved floats], contiguous.
// SMEM-staged so both the global read and global write are coalesced.
// Grid (32 kc, 8 nb, 3 w), 256 threads.
// ---------------------------------------------------------------------------
__global__ void __launch_bounds__(256)
round_w_kernel(const float* __restrict__ Wq, const float* __restrict__ Wk,
               const float* __restrict__ Wv)
{
    __shared__ float s[32][136];   // [k][n], row stride 136 (16B-multiple)
    const int kc = blockIdx.x, nb = blockIdx.y, w = blockIdx.z;
    const int tid = threadIdx.x;
    const float* W = (w == 0) ? Wq : (w == 1 ? Wk : Wv);

    #pragma unroll
    for (int i = 0; i < 4; i++) {
        int idx = tid + i * 256;             // 0..1023 float4 chunks
        int kr = idx >> 5, nc = idx & 31;
        float4 v = *(const float4*)(W + (size_t)(kc * 32 + kr) * N_W + nb * 128 + nc * 4);
        v.x = tf32r(v.x); v.y = tf32r(v.y); v.z = tf32r(v.z); v.w = tf32r(v.w);
        *(float4*)(&s[kr][nc * 4]) = v;
    }
    __syncthreads();

    float* out = g_wt + ((((size_t)w * 8 + nb) * 32 + kc) * 4096);
    #pragma unroll
    for (int i = 0; i < 4; i++) {
        int fidx = tid + i * 256;            // output float4 id
        int n = fidx >> 3, pq = fidx & 7;
        float4 o;
        #pragma unroll
        for (int e = 0; e < 4; e++) {
            int p = pq * 4 + e;
            int k = (p & ~7) + (((p & 7) >> 1) + 4 * (p & 1));  // inverse interleave
            ((float*)&o)[e] = s[k][n];
        }
        *(float4*)(out + n * 32 + pq * 4) = o;
    }
}

// ---------------------------------------------------------------------------
// Fused QKV GEMM: g_qkv[w] = x @ W[w] + b[w].
// Grid (24, 128): ntile = wsel*8 + nb. 128 threads, warp tile 64x64.
// Hot loop per ks: 8 LDS.64 (A) + 8 LDS.64 (B) -> 32 MMA.
// ---------------------------------------------------------------------------
__global__ void __launch_bounds__(128, 2)
qkv_gemm_kernel(const float* __restrict__ bq, const float* __restrict__ bk,
                const float* __restrict__ bv)
{
    extern __shared__ float smem[];
    float* As = smem;                       // [2][128][TROW]
    float* Bs = smem + 2 * TILE_F;          // [2][128][TROW]
    const uint32_t sA = smem_u32(As);
    const uint32_t sB = smem_u32(Bs);

    const int tid = threadIdx.x;
    const int wid = tid >> 5;
    const int lane = tid & 31;
    const int r = lane >> 2;                // 0..7
    const int c = lane & 3;                 // 0..3

    const int ntile = blockIdx.x;           // 0..23
    const int mtile = blockIdx.y;           // 0..127
    const int wsel  = ntile >> 3;
    const int nb    = ntile & 7;
    const int n0    = nb * BN;
    const int m0    = mtile * BM;
    const float* Wt   = g_wt + (((size_t)wsel * 8 + nb) * 32) * 4096;
    const float* bias = (wsel == 0) ? bq : (wsel == 1 ? bk : bv);

    const int wm = wid & 1;                 // 64-row group
    const int wn = wid >> 1;                // 64-col group

    auto load_tiles = [&](int kc, int buf) {
        const float* Ag = g_xr + (size_t)m0 * K_TOTAL + (size_t)kc * BK;
        const float* Bg = Wt + (size_t)kc * 4096;
        #pragma unroll
        for (int i = 0; i < 8; i++) {
            int idx = tid + i * 128;         // 0..1023
            int row = idx >> 3, q = idx & 7;
            uint32_t adst = sA + (uint32_t)(((buf * BM + row) * TROW + q * 4) * 4);
            CP_ASYNC_16(adst, Ag + (size_t)row * K_TOTAL + q * 4);
            uint32_t bdst = sB + (uint32_t)(((buf * BN + row) * TROW + q * 4) * 4);
            CP_ASYNC_16(bdst, Bg + row * 32 + q * 4);
        }
        CP_COMMIT();
    };

    float acc[4][8][4];
    #pragma unroll
    for (int mt = 0; mt < 4; mt++)
        #pragma unroll
        for (int nt = 0; nt < 8; nt++)
            #pragma unroll
            for (int i = 0; i < 4; i++) acc[mt][nt][i] = 0.f;

    load_tiles(0, 0);

    for (int kc = 0; kc < NITER; kc++) {
        const int buf = kc & 1;
        if (kc + 1 < NITER) {
            load_tiles(kc + 1, buf ^ 1);
            CP_WAIT(1);
        } else {
            CP_WAIT(0);
        }
        __syncthreads();

        const float* A_s = As + buf * TILE_F + (wm * 64 + r) * TROW;
        const float* B_s = Bs + buf * TILE_F + (wn * 64 + r) * TROW;

        #pragma unroll
        for (int ks = 0; ks < 4; ks++) {
            const int ko = ks * 8 + 2 * c;   // interleaved: (k, k+4) adjacent
            uint32_t af[4][4];
            #pragma unroll
            for (int mt = 0; mt < 4; mt++) {
                float2 p0 = *(const float2*)(A_s + (mt * 16) * TROW + ko);
                float2 p1 = *(const float2*)(A_s + (mt * 16 + 8) * TROW + ko);
                af[mt][0] = __float_as_uint(p0.x);
                af[mt][1] = __float_as_uint(p1.x);
                af[mt][2] = __float_as_uint(p0.y);
                af[mt][3] = __float_as_uint(p1.y);
            }
            uint32_t bf[8][2];
            #pragma unroll
            for (int nt = 0; nt < 8; nt++) {
                float2 pb = *(const float2*)(B_s + (nt * 8) * TROW + ko);
                bf[nt][0] = __float_as_uint(pb.x);
                bf[nt][1] = __float_as_uint(pb.y);
            }
            #pragma unroll
            for (int mt = 0; mt < 4; mt++)
                #pragma unroll
                for (int nt = 0; nt < 8; nt++)
                    mma_tf32(acc[mt][nt], af[mt], bf[nt]);
        }
        __syncthreads();
    }

    float* dst_w = g_qkv + (size_t)wsel * M_TOTAL * N_W;
    #pragma unroll
    for (int mt = 0; mt < 4; mt++) {
        const int row0 = m0 + wm * 64 + mt * 16 + r;
        #pragma unroll
        for (int nt = 0; nt < 8; nt++) {
            const int col = n0 + wn * 64 + nt * 8 + c * 2;
            const float b0 = __ldg(bias + col);
            const float b1 = __ldg(bias + col + 1);
            float2 v0 = make_float2(acc[mt][nt][0] + b0, acc[mt][nt][1] + b1);
            float2 v1 = make_float2(acc[mt][nt][2] + b0, acc[mt][nt][3] + b1);
            *(float2*)(dst_w + (size_t)row0 * N_W + col)       = v0;
            *(float2*)(dst_w + (size_t)(row0 + 8) * N_W + col) = v1;
        }
    }
}

// ---------------------------------------------------------------------------
// Head-attention (unchanged from R3): block = 8 tokens x 16 workers.
// ---------------------------------------------------------------------------
#define TPB_T 8
#define RS    68
#define TSTR  (16 * RS + 4)
#define PSTR  16
#define PTOK  (16 * PSTR + 4)
#define ATTN_SMEM_F (3 * TPB_T * TSTR + TPB_T * PTOK)
#define ATTN_SMEM_B (ATTN_SMEM_F * 4)

__global__ void __launch_bounds__(128, 2)
attn_kernel(float* __restrict__ out)
{
    extern __shared__ float sm[];
    float* sq  = sm;
    float* sk  = sm + TPB_T * TSTR;
    float* sv  = sm + 2 * TPB_T * TSTR;
    float* spT = sm + 3 * TPB_T * TSTR;

    const int tid = threadIdx.x;
    const int t0 = blockIdx.x * TPB_T;

    {
        const float* qg = g_qkv + (size_t)t0 * N_W;
        const float* kg = g_qkv + (size_t)M_TOTAL * N_W + (size_t)t0 * N_W;
        const float* vg = g_qkv + 2ull * M_TOTAL * N_W + (size_t)t0 * N_W;
        #pragma unroll
        for (int i = 0; i < 16; i++) {
            int idx = tid + i * 128;
            int tok = idx >> 8, rem = idx & 255;
            int row = rem >> 4, dq = rem & 15;
            int sa = tok * TSTR + row * RS + dq * 4;
            size_t ga = (size_t)idx * 4;
            *(float4*)(sq + sa) = *(const float4*)(qg + ga);
            *(float4*)(sk + sa) = *(const float4*)(kg + ga);
            *(float4*)(sv + sa) = *(const float4*)(vg + ga);
        }
    }
    __syncthreads();

    const int tt = tid >> 4;
    const int sub = tid & 15;
    const int ib = sub >> 2;
    const int jb = sub & 3;

    float s[4][4];
    #pragma unroll
    for (int i = 0; i < 4; i++)
        #pragma unroll
        for (int j = 0; j < 4; j++) s[i][j] = 0.f;

    {
        const float* qp = sq + tt * TSTR + (ib * 4) * RS;
        const float* kp = sk + tt * TSTR + (jb * 4) * RS;
        #pragma unroll
        for (int dq = 0; dq < 16; dq++) {
            float4 qa[4], ka[4];
            #pragma unroll
            for (int i = 0; i < 4; i++) qa[i] = *(const float4*)(qp + i * RS + dq * 4);
            #pragma unroll
            for (int j = 0; j < 4; j++) ka[j] = *(const float4*)(kp + j * RS + dq * 4);
            #pragma unroll
            for (int i = 0; i < 4; i++)
                #pragma unroll
                for (int j = 0; j < 4; j++) {
                    s[i][j] = fmaf(qa[i].x, ka[j].x, s[i][j]);
                    s[i][j] = fmaf(qa[i].y, ka[j].y, s[i][j]);
                    s[i][j] = fmaf(qa[i].z, ka[j].z, s[i][j]);
                    s[i][j] = fmaf(qa[i].w, ka[j].w, s[i][j]);
                }
        }
    }

    float p[4][4];
    #pragma unroll
    for (int i = 0; i < 4; i++) {
        float sc[4];
        #pragma unroll
        for (int j = 0; j < 4; j++) sc[j] = s[i][j] * 0.125f;
        float m = fmaxf(fmaxf(sc[0], sc[1]), fmaxf(sc[2], sc[3]));
        m = fmaxf(m, __shfl_xor_sync(0xffffffffu, m, 1));
        m = fmaxf(m, __shfl_xor_sync(0xffffffffu, m, 2));
        float sum = 0.f;
        #pragma unroll
        for (int j = 0; j < 4; j++) { p[i][j] = __expf(sc[j] - m); sum += p[i][j]; }
        sum += __shfl_xor_sync(0xffffffffu, sum, 1);
        sum += __shfl_xor_sync(0xffffffffu, sum, 2);
        float inv = __frcp_rn(sum);
        #pragma unroll
        for (int j = 0; j < 4; j++) p[i][j] *= inv;
    }
    {
        float* pt = spT + tt * PTOK;
        #pragma unroll
        for (int j = 0; j < 4; j++) {
            float4 v = make_float4(p[0][j], p[1][j], p[2][j], p[3][j]);
            *(float4*)(pt + (jb * 4 + j) * PSTR + ib * 4) = v;
        }
    }
    __syncwarp();

    {
        const int c0 = sub * 4;
        const float* pt = spT + tt * PTOK;
        const float* vp = sv + tt * TSTR + c0;
        float4 acc[16];
        #pragma unroll
        for (int i = 0; i < 16; i++) acc[i] = make_float4(0.f, 0.f, 0.f, 0.f);
        #pragma unroll
        for (int j = 0; j < 16; j++) {
            float4 vj = *(const float4*)(vp + j * RS);
            const float* pr = pt + j * PSTR;
            float4 p0 = *(const float4*)(pr);
            float4 p1 = *(const float4*)(pr + 4);
            float4 p2 = *(const float4*)(pr + 8);
            float4 p3 = *(const float4*)(pr + 12);
            const float pj[16] = {p0.x,p0.y,p0.z,p0.w, p1.x,p1.y,p1.z,p1.w,
                                  p2.x,p2.y,p2.z,p2.w, p3.x,p3.y,p3.z,p3.w};
            #pragma unroll
            for (int i = 0; i < 16; i++) {
                acc[i].x = fmaf(pj[i], vj.x, acc[i].x);
                acc[i].y = fmaf(pj[i], vj.y, acc[i].y);
                acc[i].z = fmaf(pj[i], vj.z, acc[i].z);
                acc[i].w = fmaf(pj[i], vj.w, acc[i].w);
            }
        }
        float* ob = out + (size_t)(t0 + tt) * N_W + c0;
        #pragma unroll
        for (int i = 0; i < 16; i++)
            *(float4*)(ob + i * 64) = acc[i];
    }
}

// ---------------------------------------------------------------------------
// Launch
// ---------------------------------------------------------------------------
extern "C" void kernel_launch(void* const* d_in, const int* in_sizes, int n_in,
                              void* d_out, int out_size)
{
    const float* x  = (const float*)d_in[0];
    const float* Wq = (const float*)d_in[1];
    const float* bq = (const float*)d_in[2];
    const float* Wk = (const float*)d_in[3];
    const float* bk = (const float*)d_in[4];
    const float* Wv = (const float*)d_in[5];
    const float* bv = (const float*)d_in[6];
    float* out = (float*)d_out;

    cudaFuncSetAttribute(qkv_gemm_kernel,
                         cudaFuncAttributeMaxDynamicSharedMemorySize, SMEM_BYTES);
    cudaFuncSetAttribute(attn_kernel,
                         cudaFuncAttributeMaxDynamicSharedMemorySize, ATTN_SMEM_B);

    round_x_kernel<<<(M_TOTAL * K_TOTAL / 8) / 256, 256>>>(x);
    {
        dim3 gw(32, 8, 3);
        round_w_kernel<<<gw, 256>>>(Wq, Wk, Wv);
    }
    dim3 grid(24, 128);
    qkv_gemm_kernel<<<grid, 128, SMEM_BYTES>>>(bq, bk, bv);
    attn_kernel<<<M_TOTAL / TPB_T, 128, ATTN_SMEM_B>>>(out);
}